// round 15
// baseline (speedup 1.0000x reference)
#include <cuda_runtime.h>
#include <cuda_fp16.h>
#include <cstdint>

#define S_LEN 2048
#define HID 3072
#define NH 24
#define NKV 8
#define HD 128
#define OPSZ 5120
#define QK_COLS 4096
#define SCALING 0.08838834764831845f

// ---------------------------------------------------------------------------
// Scratch (__device__ globals; runtime allocation forbidden)
// ---------------------------------------------------------------------------
__device__ float  g_qkv[(size_t)S_LEN * OPSZ];                                 // 42 MB
__device__ __half g_hidh [(size_t)S_LEN * HID], g_hidl [(size_t)S_LEN * HID];
__device__ __half g_wqkvh[(size_t)OPSZ * HID];                                 // B: hi only
__device__ __half g_woh  [(size_t)HID * HID];                                  // B: hi only
__device__ __half g_qkh  [(size_t)S_LEN * QK_COLS], g_qkl[(size_t)S_LEN * QK_COLS];
__device__ __half g_vTh  [(size_t)NKV * HD * S_LEN];                           // B: hi only
__device__ __half g_Ph   [(size_t)NH * S_LEN * S_LEN];                         // 201 MB (hi only)
__device__ __half g_aoh  [(size_t)S_LEN * HID];                                // hi only

// ---------------------------------------------------------------------------
// helpers
// ---------------------------------------------------------------------------
__device__ __forceinline__ uint32_t smem_u32(const void* p) {
    uint32_t a;
    asm("{ .reg .u64 t; cvta.to.shared.u64 t, %1; cvt.u32.u64 %0, t; }"
        : "=r"(a) : "l"(p));
    return a;
}
__device__ __forceinline__ void ldm4(uint32_t* r, uint32_t addr) {
    asm volatile("ldmatrix.sync.aligned.m8n8.x4.shared.b16 {%0,%1,%2,%3}, [%4];"
        : "=r"(r[0]), "=r"(r[1]), "=r"(r[2]), "=r"(r[3]) : "r"(addr));
}
__device__ __forceinline__ void mma16816(float* c, const uint32_t* a,
                                         const uint32_t* b) {
    asm volatile(
        "mma.sync.aligned.m16n8k16.row.col.f32.f16.f16.f32 "
        "{%0,%1,%2,%3}, {%4,%5,%6,%7}, {%8,%9}, {%0,%1,%2,%3};"
        : "+f"(c[0]), "+f"(c[1]), "+f"(c[2]), "+f"(c[3])
        : "r"(a[0]), "r"(a[1]), "r"(a[2]), "r"(a[3]), "r"(b[0]), "r"(b[1]));
}
// pack two fp32 -> f16x2 (lo half = a, hi half = b), round-to-nearest
__device__ __forceinline__ uint32_t pk2h(float a, float b) {
    uint32_t r;
    asm("cvt.rn.f16x2.f32 %0, %1, %2;" : "=r"(r) : "f"(b), "f"(a));
    return r;
}
__device__ __forceinline__ float h2f_lo(uint32_t p) {
    return __half2float(__ushort_as_half((unsigned short)(p & 0xffffu)));
}
__device__ __forceinline__ float h2f_hi(uint32_t p) {
    return __half2float(__ushort_as_half((unsigned short)(p >> 16)));
}
#define CP16(dst, src) \
    asm volatile("cp.async.cg.shared.global [%0], [%1], 16;" \
                 :: "r"(dst), "l"(src) : "memory")
#define CP_COMMIT() asm volatile("cp.async.commit_group;" ::: "memory")
#define CP_WAIT2()  asm volatile("cp.async.wait_group 2;" ::: "memory")

// ---------------------------------------------------------------------------
// fp32 -> (f16 hi, f16 lo) split, 4 elems/thread
// ---------------------------------------------------------------------------
__global__ __launch_bounds__(256) void conv_split_hl(
    const float* __restrict__ src, __half* __restrict__ h,
    __half* __restrict__ l, int n4)
{
    int i = blockIdx.x * 256 + threadIdx.x;
    if (i >= n4) return;
    float4 x = ((const float4*)src)[i];
    uint32_t p0 = pk2h(x.x, x.y), p1 = pk2h(x.z, x.w);
    float l0 = x.x - h2f_lo(p0);
    float l1 = x.y - h2f_hi(p0);
    float l2 = x.z - h2f_lo(p1);
    float l3 = x.w - h2f_hi(p1);
    uint2 hh; hh.x = p0; hh.y = p1;
    uint2 ll; ll.x = pk2h(l0, l1); ll.y = pk2h(l2, l3);
    ((uint2*)h)[i] = hh;
    ((uint2*)l)[i] = ll;
}

// fp32 -> f16 hi only (B-side operands), 4 elems/thread
__global__ __launch_bounds__(256) void conv_split_h(
    const float* __restrict__ src, __half* __restrict__ h, int n4)
{
    int i = blockIdx.x * 256 + threadIdx.x;
    if (i >= n4) return;
    float4 x = ((const float4*)src)[i];
    uint2 hh; hh.x = pk2h(x.x, x.y); hh.y = pk2h(x.z, x.w);
    ((uint2*)h)[i] = hh;
}

// ---------------------------------------------------------------------------
// Zero-fill attn[c >= blockend(r)] (strictly above each diagonal 128-block).
// Disjoint from every QK-tile and softmax write; runs hidden under QKV GEMM.
// ---------------------------------------------------------------------------
__global__ __launch_bounds__(256) void zfill_upper(float* __restrict__ attn)
{
    const int r = blockIdx.x;
    const int h = blockIdx.y;
    const int blockend = ((r >> 7) + 1) << 7;
    if (blockend >= S_LEN) return;
    float4* row4 = (float4*)(attn + ((size_t)h * S_LEN + r) * S_LEN);
    const float4 z = make_float4(0.f, 0.f, 0.f, 0.f);
    for (int c4 = (blockend >> 2) + threadIdx.x; c4 < (S_LEN >> 2); c4 += 256)
        row4[c4] = z;
}

// ---------------------------------------------------------------------------
// Fused RoPE + split on Q/K columns (0..4095). Q cols get hi+lo, K hi only.
// ---------------------------------------------------------------------------
__global__ __launch_bounds__(256) void rope_split(
    const float* __restrict__ qkv, const float* __restrict__ cosb,
    const float* __restrict__ sinb,
    __half* __restrict__ qh, __half* __restrict__ ql)
{
    int idx = blockIdx.x * 256 + threadIdx.x;   // S_LEN * 1024
    int s = idx >> 10;
    int c = (idx & 1023) * 4;
    int d = c & 127;
    const float* row = qkv + (size_t)s * OPSZ;
    float4 x = *(const float4*)(row + c);
    if (d < 96) {
        float4 cc = *(const float4*)(cosb + s * 96 + d);
        float4 ss = *(const float4*)(sinb + s * 96 + d);
        if (d < 48) {
            float4 p = *(const float4*)(row + c + 48);
            x.x = x.x * cc.x - p.x * ss.x;
            x.y = x.y * cc.y - p.y * ss.y;
            x.z = x.z * cc.z - p.z * ss.z;
            x.w = x.w * cc.w - p.w * ss.w;
        } else {
            float4 p = *(const float4*)(row + c - 48);
            x.x = x.x * cc.x + p.x * ss.x;
            x.y = x.y * cc.y + p.y * ss.y;
            x.z = x.z * cc.z + p.z * ss.z;
            x.w = x.w * cc.w + p.w * ss.w;
        }
    }
    uint32_t p0 = pk2h(x.x, x.y), p1 = pk2h(x.z, x.w);
    size_t o = ((size_t)s * QK_COLS + c) >> 2;
    uint2 hh; hh.x = p0; hh.y = p1;
    ((uint2*)qh)[o] = hh;
    if (c < HID) {                      // lo needed only for Q (A-side)
        float l0 = x.x - h2f_lo(p0);
        float l1 = x.y - h2f_hi(p0);
        float l2 = x.z - h2f_lo(p1);
        float l3 = x.w - h2f_hi(p1);
        uint2 ll; ll.x = pk2h(l0, l1); ll.y = pk2h(l2, l3);
        ((uint2*)ql)[o] = ll;
    }
}

// ---------------------------------------------------------------------------
// V transpose + split (hi only): vT[kv*HD+d][s] = qkv[s][4096+kv*HD+d]
// ---------------------------------------------------------------------------
__global__ __launch_bounds__(256) void vsplit_T(
    const float* __restrict__ qkv, __half* __restrict__ vh)
{
    __shared__ float tile[32][33];
    const int t0 = blockIdx.x * 32;
    const int s0 = blockIdx.y * 32;
    const int tx = threadIdx.x, ty = threadIdx.y;   // (32, 8)
#pragma unroll
    for (int j = 0; j < 4; j++)
        tile[ty + 8 * j][tx] =
            qkv[(size_t)(s0 + ty + 8 * j) * OPSZ + 4096 + t0 + tx];
    __syncthreads();
#pragma unroll
    for (int j = 0; j < 4; j++) {
        float v = tile[tx][ty + 8 * j];
        vh[(size_t)(t0 + ty + 8 * j) * S_LEN + s0 + tx] = __float2half_rn(v);
    }
}

// ---------------------------------------------------------------------------
// Generic NT GEMM, fp16: C = alpha * (Ah [+Al]) [M,K] * Bh[N,K]^T
// Al term applied only for tiles with col0 < nloCols (per-tile term count).
// 128x128 tile, 512 threads (16 warps, warp tile 32x32), KC=32,
// 4-stage cp.async pipeline, 80B SMEM row pitch.
// flags: 1 = causal tile skip, 2 = K limited to row0+128,
//        4 = f16 split output (hi to Ch; lo to Cl only if !(flags&8)).
// ---------------------------------------------------------------------------
#define KC 32
#define TILE80 10240u              // 128 rows * 80 B
#define STAGE_B (3u * TILE80)      // Ah Al Bh = 30720
#define NSTAGE  4
#define GEMM_SMEM (NSTAGE * STAGE_B)   // 122880

__global__ __launch_bounds__(512) void gemm_f16(
    const __half* __restrict__ Ah, const __half* __restrict__ Al,
    int lda, long long sAz,
    const __half* __restrict__ Bh, int ldb, long long sBz, int kvdiv,
    float* __restrict__ Cf, __half* __restrict__ Ch,
    __half* __restrict__ Cl, int ldc, long long sCz,
    int K, float alpha, int flags, int nloCols)
{
    const int row0 = blockIdx.y << 7;
    const int col0 = blockIdx.x << 7;
    if ((flags & 1) && col0 > row0) return;
    const bool useAl = (col0 < nloCols);
    const int z = blockIdx.z;
    const size_t za = (size_t)z * sAz;
    const size_t zb = (size_t)(z / kvdiv) * sBz;
    const size_t zc = (size_t)z * sCz;
    Ah += za; Al += za; Bh += zb;
    const int Keff = (flags & 2) ? ((K < row0 + 128) ? K : row0 + 128) : K;
    const int nCh  = Keff >> 5;

    extern __shared__ char smem[];
    const uint32_t base = smem_u32(smem);

    const int tid  = threadIdx.x;
    const int warp = tid >> 5;
    const int lane = tid & 31;
    const int wm   = warp >> 2;      // 0..3
    const int wn   = warp & 3;       // 0..3

    // producer mapping: row = tid>>2 (0..127), 16B chunk = tid&3
    const int prow = tid >> 2;
    const int pq   = tid & 3;
    const uint32_t pst = (uint32_t)prow * 80u + (uint32_t)pq * 16u;
    const __half* pAh = Ah + (size_t)(row0 + prow) * lda + pq * 8;
    const __half* pAl = Al + (size_t)(row0 + prow) * lda + pq * 8;
    const __half* pBh = Bh + (size_t)(col0 + prow) * ldb + pq * 8;

    // prologue: stages 0..2 (nCh >= 4 for every launch in this problem)
#pragma unroll
    for (int s = 0; s < NSTAGE - 1; s++) {
        const int kO = s * KC;
        const uint32_t st = base + (uint32_t)s * STAGE_B;
        CP16(st + pst,               pAh + kO);
        if (useAl) CP16(st + TILE80 + pst, pAl + kO);
        CP16(st + 2u * TILE80 + pst, pBh + kO);
        CP_COMMIT();
    }

    // acc[mt][g] = n-subtile 2g, acc2[mt][g] = n-subtile 2g+1
    float acc [2][2][4];
    float acc2[2][2][4];
#pragma unroll
    for (int mt = 0; mt < 2; mt++)
#pragma unroll
        for (int g = 0; g < 2; g++)
#pragma unroll
            for (int r = 0; r < 4; r++) { acc[mt][g][r] = 0.f; acc2[mt][g][r] = 0.f; }

    const uint32_t aRow  = (uint32_t)(wm * 32 + (lane & 15));
    const uint32_t aSlot = (uint32_t)(lane >> 4);
    const uint32_t bRow  = (uint32_t)(wn * 32 + (lane & 7) + ((lane >> 4) << 3));
    const uint32_t bSlot = (uint32_t)((lane >> 3) & 1);

    for (int i = 0; i < nCh; i++) {
        CP_WAIT2();                 // chunk i landed
        __syncthreads();            // all warps done with the stage being refilled
        if (i + NSTAGE - 1 < nCh) {
            const int kO = (i + NSTAGE - 1) * KC;
            const uint32_t st =
                base + (uint32_t)((i + NSTAGE - 1) & (NSTAGE - 1)) * STAGE_B;
            CP16(st + pst,               pAh + kO);
            if (useAl) CP16(st + TILE80 + pst, pAl + kO);
            CP16(st + 2u * TILE80 + pst, pBh + kO);
        }
        CP_COMMIT();

        const uint32_t buf = base + (uint32_t)(i & (NSTAGE - 1)) * STAGE_B;
#pragma unroll
        for (int s = 0; s < 2; s++) {
            uint32_t a[2][4];       // Ah, later overwritten by Al
            uint32_t b2[2][4];      // Bh (two subtiles per group)
            // phase 1: Ah x Bh
#pragma unroll
            for (int mt = 0; mt < 2; mt++)
                ldm4(a[mt], buf + (aRow + (uint32_t)(mt * 16)) * 80u
                                + (2u * s + aSlot) * 16u);
#pragma unroll
            for (int g = 0; g < 2; g++)
                ldm4(b2[g], buf + 2u * TILE80
                                + (bRow + (uint32_t)(g * 16)) * 80u
                                + (2u * s + bSlot) * 16u);
#pragma unroll
            for (int mt = 0; mt < 2; mt++)
#pragma unroll
                for (int g = 0; g < 2; g++) {
                    mma16816(acc [mt][g], a[mt], b2[g]);
                    mma16816(acc2[mt][g], a[mt], b2[g] + 2);
                }
            // phase 2: Al x Bh (only when this tile carries the lo term)
            if (useAl) {
#pragma unroll
                for (int mt = 0; mt < 2; mt++)
                    ldm4(a[mt], buf + TILE80
                                    + (aRow + (uint32_t)(mt * 16)) * 80u
                                    + (2u * s + aSlot) * 16u);
#pragma unroll
                for (int mt = 0; mt < 2; mt++)
#pragma unroll
                    for (int g = 0; g < 2; g++) {
                        mma16816(acc [mt][g], a[mt], b2[g]);
                        mma16816(acc2[mt][g], a[mt], b2[g] + 2);
                    }
            }
        }
    }

    // epilogue: group g covers n-subtiles {2g (acc), 2g+1 (acc2)}
#pragma unroll
    for (int mt = 0; mt < 2; mt++) {
        const int rbase = row0 + wm * 32 + mt * 16 + (lane >> 2);
#pragma unroll
        for (int g = 0; g < 2; g++) {
#pragma unroll
            for (int half = 0; half < 2; half++) {
                const float* a4 = half ? acc2[mt][g] : acc[mt][g];
                const int nt = 2 * g + half;
                const int cbase = col0 + wn * 32 + nt * 8 + (lane & 3) * 2;
                float v00 = alpha * a4[0];
                float v01 = alpha * a4[1];
                float v10 = alpha * a4[2];
                float v11 = alpha * a4[3];
                if (flags & 4) {
                    uint32_t h0 = pk2h(v00, v01);
                    uint32_t h1 = pk2h(v10, v11);
                    *(uint32_t*)(Ch + zc + (size_t)rbase * ldc + cbase)       = h0;
                    *(uint32_t*)(Ch + zc + (size_t)(rbase + 8) * ldc + cbase) = h1;
                    if (!(flags & 8)) {
                        uint32_t l0 = pk2h(v00 - h2f_lo(h0), v01 - h2f_hi(h0));
                        uint32_t l1 = pk2h(v10 - h2f_lo(h1), v11 - h2f_hi(h1));
                        *(uint32_t*)(Cl + zc + (size_t)rbase * ldc + cbase)       = l0;
                        *(uint32_t*)(Cl + zc + (size_t)(rbase + 8) * ldc + cbase) = l1;
                    }
                } else {
                    float2 v0; v0.x = v00; v0.y = v01;
                    float2 v1; v1.x = v10; v1.y = v11;
                    *(float2*)(Cf + zc + (size_t)rbase * ldc + cbase)       = v0;
                    *(float2*)(Cf + zc + (size_t)(rbase + 8) * ldc + cbase) = v1;
                }
            }
        }
    }
}

// ---------------------------------------------------------------------------
// Causal softmax in place; stores only c < blockend (zfill_upper owns the
// rest). Emits f16 P (hi only) over the same range.
// ---------------------------------------------------------------------------
__global__ __launch_bounds__(256) void softmax_causal(
    float* __restrict__ attn, __half* __restrict__ Ph)
{
    const int r = blockIdx.x;
    const int h = blockIdx.y;
    const size_t ro = ((size_t)h * S_LEN + r) * S_LEN;
    float* row = attn + ro;
    const int nv  = r + 1;
    const int blockend = ((r >> 7) + 1) << 7;   // end of diagonal 128-block
    const int tid = threadIdx.x;

    float v[8];
    float mx = -1e30f;
#pragma unroll
    for (int i = 0; i < 8; i++) {
        int c = tid + i * 256;
        v[i] = (c < nv) ? row[c] : -1e30f;
        mx = fmaxf(mx, v[i]);
    }

    __shared__ float red[256];
    red[tid] = mx;
    __syncthreads();
#pragma unroll
    for (int s2 = 128; s2 > 0; s2 >>= 1) {
        if (tid < s2) red[tid] = fmaxf(red[tid], red[tid + s2]);
        __syncthreads();
    }
    mx = red[0];
    __syncthreads();

    float sum = 0.f;
#pragma unroll
    for (int i = 0; i < 8; i++) {
        int c = tid + i * 256;
        v[i] = (c < nv) ? expf(v[i] - mx) : 0.f;
        sum += v[i];
    }
    red[tid] = sum;
    __syncthreads();
#pragma unroll
    for (int s2 = 128; s2 > 0; s2 >>= 1) {
        if (tid < s2) red[tid] += red[tid + s2];
        __syncthreads();
    }
    const float inv = 1.f / red[0];

#pragma unroll
    for (int i = 0; i < 8; i++) {
        int c = tid + i * 256;
        if (c < blockend) {
            float val = v[i] * inv;
            row[c] = val;
            Ph[ro + c] = __float2half_rn(val);
        }
    }
}

// ---------------------------------------------------------------------------
// Launch
// Inputs: hidden_states, cos, sin, attention_mask, w_qkv, w_o
// Output: [out (1,2048,3072)] ++ [attn_weights (1,24,2048,2048)]
// ---------------------------------------------------------------------------
extern "C" void kernel_launch(void* const* d_in, const int* in_sizes, int n_in,
                              void* d_out, int out_size)
{
    const float* hidden = (const float*)d_in[0];
    const float* cosb   = (const float*)d_in[1];
    const float* sinb   = (const float*)d_in[2];
    const float* wqkv   = (const float*)d_in[4];
    const float* wo     = (const float*)d_in[5];

    float* out  = (float*)d_out;
    float* attn = out + (size_t)S_LEN * HID;

    float* qkv;
    __half *hidh, *hidl, *wqkvh, *woh;
    __half *qkh, *qkl, *vTh, *Ph, *aoh;
    cudaGetSymbolAddress((void**)&qkv,   g_qkv);
    cudaGetSymbolAddress((void**)&hidh,  g_hidh);
    cudaGetSymbolAddress((void**)&hidl,  g_hidl);
    cudaGetSymbolAddress((void**)&wqkvh, g_wqkvh);
    cudaGetSymbolAddress((void**)&woh,   g_woh);
    cudaGetSymbolAddress((void**)&qkh,   g_qkh);
    cudaGetSymbolAddress((void**)&qkl,   g_qkl);
    cudaGetSymbolAddress((void**)&vTh,   g_vTh);
    cudaGetSymbolAddress((void**)&Ph,    g_Ph);
    cudaGetSymbolAddress((void**)&aoh,   g_aoh);

    cudaFuncSetAttribute(gemm_f16, cudaFuncAttributeMaxDynamicSharedMemorySize,
                         GEMM_SMEM);

    // one-time streams + events
    static cudaStream_t s2 = nullptr, s3 = nullptr;
    static cudaEvent_t evF = nullptr, evJ = nullptr, evS = nullptr,
                       evQKV = nullptr, evVT = nullptr, evZ = nullptr;
    if (!s2) {
        cudaStreamCreateWithFlags(&s2, cudaStreamNonBlocking);
        cudaStreamCreateWithFlags(&s3, cudaStreamNonBlocking);
        cudaEventCreateWithFlags(&evF,   cudaEventDisableTiming);
        cudaEventCreateWithFlags(&evJ,   cudaEventDisableTiming);
        cudaEventCreateWithFlags(&evS,   cudaEventDisableTiming);
        cudaEventCreateWithFlags(&evQKV, cudaEventDisableTiming);
        cudaEventCreateWithFlags(&evVT,  cudaEventDisableTiming);
        cudaEventCreateWithFlags(&evZ,   cudaEventDisableTiming);
    }

    // fork s2 for the w_o split (overlaps the input splits + QKV)
    cudaEventRecord(evF, 0);
    cudaStreamWaitEvent(s2, evF, 0);
    conv_split_h<<<(HID * HID / 4 + 255) / 256, 256, 0, s2>>>(
        wo, woh, HID * HID / 4);
    cudaEventRecord(evJ, s2);

    // main: splits needed before QKV (DRAM-heavy; keep s3 idle until done)
    conv_split_hl<<<(S_LEN * HID / 4 + 255) / 256, 256>>>(hidden, hidh, hidl,
                                                          S_LEN * HID / 4);
    conv_split_h<<<(OPSZ * HID / 4 + 255) / 256, 256>>>(wqkv, wqkvh,
                                                        OPSZ * HID / 4);
    cudaEventRecord(evS, 0);

    // s3: zero-fill strictly-upper attn, hidden under the QKV GEMM
    cudaStreamWaitEvent(s3, evS, 0);
    zfill_upper<<<dim3(S_LEN, NH), 256, 0, s3>>>(attn);
    cudaEventRecord(evZ, s3);

    // 1. qkv = hidden @ w_qkv^T (Q tiles 2-term A, K/V tiles 1-term)
    gemm_f16<<<dim3(OPSZ / 128, S_LEN / 128, 1), 512, GEMM_SMEM>>>(
        hidh, hidl, HID, 0, wqkvh, HID, 0, 1,
        qkv, nullptr, nullptr, OPSZ, 0, HID, 1.0f, 0, HID);
    cudaEventRecord(evQKV, 0);

    // s2: vT split (only PV needs it) overlapped with rope + QK
    cudaStreamWaitEvent(s2, evQKV, 0);
    vsplit_T<<<dim3((NKV * HD) / 32, S_LEN / 32), dim3(32, 8), 0, s2>>>(qkv, vTh);
    cudaEventRecord(evVT, s2);

    // 2. RoPE + split Q(hi/lo)/K(hi)
    rope_split<<<S_LEN * 1024 / 256, 256>>>(qkv, cosb, sinb, qkh, qkl);

    // 4. scores = Q K^T * scale (causal tiles only) -> attn fp32 (2-term A)
    gemm_f16<<<dim3(S_LEN / 128, S_LEN / 128, NH), 512, GEMM_SMEM>>>(
        qkh, qkl, QK_COLS, HD,
        qkh + HID, QK_COLS, HD, 3,
        attn, nullptr, nullptr, S_LEN, (long long)S_LEN * S_LEN,
        HD, SCALING, 1, 1 << 30);

    // 5. softmax in place (stores only c < blockend) + P hi emit
    softmax_causal<<<dim3(S_LEN, NH), 256>>>(attn, Ph);

    // 6. ao(hi) = P @ V (K limited to row0+128; 1-term)
    cudaStreamWaitEvent(0, evVT, 0);
    gemm_f16<<<dim3(HD / 128, S_LEN / 128, NH), 512, GEMM_SMEM>>>(
        Ph, Ph, S_LEN, (long long)S_LEN * S_LEN,
        vTh, S_LEN, (long long)HD * S_LEN, 3,
        nullptr, aoh, nullptr, HID, HD,
        S_LEN, 1.0f, 2 | 4 | 8, 0);

    // joins: w_o split, zfill
    cudaStreamWaitEvent(0, evJ, 0);
    cudaStreamWaitEvent(0, evZ, 0);

    // 7. out = ao @ w_o^T (1-term)
    gemm_f16<<<dim3(HID / 128, S_LEN / 128, 1), 512, GEMM_SMEM>>>(
        aoh, aoh, HID, 0, woh, HID, 0, 1,
        out, nullptr, nullptr, HID, 0, HID, 1.0f, 0, 0);
}

// round 16
// speedup vs baseline: 1.0550x; 1.0550x over previous
#include <cuda_runtime.h>
#include <cuda_fp16.h>
#include <cstdint>

#define S_LEN 2048
#define HID 3072
#define NH 24
#define NKV 8
#define HD 128
#define OPSZ 5120
#define QK_COLS 4096
#define SCALING 0.08838834764831845f

// ---------------------------------------------------------------------------
// Scratch (__device__ globals; runtime allocation forbidden)
// ---------------------------------------------------------------------------
__device__ float  g_qkv[(size_t)S_LEN * OPSZ];                                 // 42 MB
__device__ __half g_hidh [(size_t)S_LEN * HID];                                // hi only
__device__ __half g_wqkvh[(size_t)OPSZ * HID];                                 // B: hi only
__device__ __half g_woh  [(size_t)HID * HID];                                  // B: hi only
__device__ __half g_qkh  [(size_t)S_LEN * QK_COLS], g_qkl[(size_t)S_LEN * QK_COLS];
__device__ __half g_vTh  [(size_t)NKV * HD * S_LEN];                           // B: hi only
__device__ __half g_Ph   [(size_t)NH * S_LEN * S_LEN];                         // 201 MB (hi only)
__device__ __half g_aoh  [(size_t)S_LEN * HID];                                // hi only

// ---------------------------------------------------------------------------
// helpers
// ---------------------------------------------------------------------------
__device__ __forceinline__ uint32_t smem_u32(const void* p) {
    uint32_t a;
    asm("{ .reg .u64 t; cvta.to.shared.u64 t, %1; cvt.u32.u64 %0, t; }"
        : "=r"(a) : "l"(p));
    return a;
}
__device__ __forceinline__ void ldm4(uint32_t* r, uint32_t addr) {
    asm volatile("ldmatrix.sync.aligned.m8n8.x4.shared.b16 {%0,%1,%2,%3}, [%4];"
        : "=r"(r[0]), "=r"(r[1]), "=r"(r[2]), "=r"(r[3]) : "r"(addr));
}
__device__ __forceinline__ void mma16816(float* c, const uint32_t* a,
                                         const uint32_t* b) {
    asm volatile(
        "mma.sync.aligned.m16n8k16.row.col.f32.f16.f16.f32 "
        "{%0,%1,%2,%3}, {%4,%5,%6,%7}, {%8,%9}, {%0,%1,%2,%3};"
        : "+f"(c[0]), "+f"(c[1]), "+f"(c[2]), "+f"(c[3])
        : "r"(a[0]), "r"(a[1]), "r"(a[2]), "r"(a[3]), "r"(b[0]), "r"(b[1]));
}
// pack two fp32 -> f16x2 (lo half = a, hi half = b), round-to-nearest
__device__ __forceinline__ uint32_t pk2h(float a, float b) {
    uint32_t r;
    asm("cvt.rn.f16x2.f32 %0, %1, %2;" : "=r"(r) : "f"(b), "f"(a));
    return r;
}
__device__ __forceinline__ float h2f_lo(uint32_t p) {
    return __half2float(__ushort_as_half((unsigned short)(p & 0xffffu)));
}
__device__ __forceinline__ float h2f_hi(uint32_t p) {
    return __half2float(__ushort_as_half((unsigned short)(p >> 16)));
}
#define CP16(dst, src) \
    asm volatile("cp.async.cg.shared.global [%0], [%1], 16;" \
                 :: "r"(dst), "l"(src) : "memory")
#define CP_COMMIT() asm volatile("cp.async.commit_group;" ::: "memory")
#define CP_WAIT2()  asm volatile("cp.async.wait_group 2;" ::: "memory")

// fp32 -> f16 hi only, 4 elems/thread
__global__ __launch_bounds__(256) void conv_split_h(
    const float* __restrict__ src, __half* __restrict__ h, int n4)
{
    int i = blockIdx.x * 256 + threadIdx.x;
    if (i >= n4) return;
    float4 x = ((const float4*)src)[i];
    uint2 hh; hh.x = pk2h(x.x, x.y); hh.y = pk2h(x.z, x.w);
    ((uint2*)h)[i] = hh;
}

// ---------------------------------------------------------------------------
// Fused RoPE + split on Q/K columns (0..4095). Q cols get hi+lo, K hi only.
// ---------------------------------------------------------------------------
__global__ __launch_bounds__(256) void rope_split(
    const float* __restrict__ qkv, const float* __restrict__ cosb,
    const float* __restrict__ sinb,
    __half* __restrict__ qh, __half* __restrict__ ql)
{
    int idx = blockIdx.x * 256 + threadIdx.x;   // S_LEN * 1024
    int s = idx >> 10;
    int c = (idx & 1023) * 4;
    int d = c & 127;
    const float* row = qkv + (size_t)s * OPSZ;
    float4 x = *(const float4*)(row + c);
    if (d < 96) {
        float4 cc = *(const float4*)(cosb + s * 96 + d);
        float4 ss = *(const float4*)(sinb + s * 96 + d);
        if (d < 48) {
            float4 p = *(const float4*)(row + c + 48);
            x.x = x.x * cc.x - p.x * ss.x;
            x.y = x.y * cc.y - p.y * ss.y;
            x.z = x.z * cc.z - p.z * ss.z;
            x.w = x.w * cc.w - p.w * ss.w;
        } else {
            float4 p = *(const float4*)(row + c - 48);
            x.x = x.x * cc.x + p.x * ss.x;
            x.y = x.y * cc.y + p.y * ss.y;
            x.z = x.z * cc.z + p.z * ss.z;
            x.w = x.w * cc.w + p.w * ss.w;
        }
    }
    uint32_t p0 = pk2h(x.x, x.y), p1 = pk2h(x.z, x.w);
    size_t o = ((size_t)s * QK_COLS + c) >> 2;
    uint2 hh; hh.x = p0; hh.y = p1;
    ((uint2*)qh)[o] = hh;
    if (c < HID) {                      // lo needed only for Q (A-side)
        float l0 = x.x - h2f_lo(p0);
        float l1 = x.y - h2f_hi(p0);
        float l2 = x.z - h2f_lo(p1);
        float l3 = x.w - h2f_hi(p1);
        uint2 ll; ll.x = pk2h(l0, l1); ll.y = pk2h(l2, l3);
        ((uint2*)ql)[o] = ll;
    }
}

// ---------------------------------------------------------------------------
// V transpose + split (hi only): vT[kv*HD+d][s] = qkv[s][4096+kv*HD+d]
// ---------------------------------------------------------------------------
__global__ __launch_bounds__(256) void vsplit_T(
    const float* __restrict__ qkv, __half* __restrict__ vh)
{
    __shared__ float tile[32][33];
    const int t0 = blockIdx.x * 32;
    const int s0 = blockIdx.y * 32;
    const int tx = threadIdx.x, ty = threadIdx.y;   // (32, 8)
#pragma unroll
    for (int j = 0; j < 4; j++)
        tile[ty + 8 * j][tx] =
            qkv[(size_t)(s0 + ty + 8 * j) * OPSZ + 4096 + t0 + tx];
    __syncthreads();
#pragma unroll
    for (int j = 0; j < 4; j++) {
        float v = tile[tx][ty + 8 * j];
        vh[(size_t)(t0 + ty + 8 * j) * S_LEN + s0 + tx] = __float2half_rn(v);
    }
}

// ---------------------------------------------------------------------------
// Generic NT GEMM, fp16: C = alpha * (Ah [+Al]) [M,K] * Bh[N,K]^T
// Al term applied only for tiles with col0 < nloCols (per-tile term count).
// 128x128 tile, 512 threads (16 warps, warp tile 32x32), KC=32,
// 4-stage cp.async pipeline, 80B SMEM row pitch.
// flags: 1 = causal tile skip, 2 = K limited to row0+128,
//        4 = f16 split output (hi to Ch; lo to Cl only if !(flags&8)).
// ---------------------------------------------------------------------------
#define KC 32
#define TILE80 10240u              // 128 rows * 80 B
#define STAGE_B (3u * TILE80)      // Ah Al Bh = 30720
#define NSTAGE  4
#define GEMM_SMEM (NSTAGE * STAGE_B)   // 122880

__global__ __launch_bounds__(512) void gemm_f16(
    const __half* __restrict__ Ah, const __half* __restrict__ Al,
    int lda, long long sAz,
    const __half* __restrict__ Bh, int ldb, long long sBz, int kvdiv,
    float* __restrict__ Cf, __half* __restrict__ Ch,
    __half* __restrict__ Cl, int ldc, long long sCz,
    int K, float alpha, int flags, int nloCols)
{
    const int row0 = blockIdx.y << 7;
    const int col0 = blockIdx.x << 7;
    if ((flags & 1) && col0 > row0) return;
    const bool useAl = (col0 < nloCols);
    const int z = blockIdx.z;
    const size_t za = (size_t)z * sAz;
    const size_t zb = (size_t)(z / kvdiv) * sBz;
    const size_t zc = (size_t)z * sCz;
    Ah += za; Al += za; Bh += zb;
    const int Keff = (flags & 2) ? ((K < row0 + 128) ? K : row0 + 128) : K;
    const int nCh  = Keff >> 5;

    extern __shared__ char smem[];
    const uint32_t base = smem_u32(smem);

    const int tid  = threadIdx.x;
    const int warp = tid >> 5;
    const int lane = tid & 31;
    const int wm   = warp >> 2;      // 0..3
    const int wn   = warp & 3;       // 0..3

    // producer mapping: row = tid>>2 (0..127), 16B chunk = tid&3
    const int prow = tid >> 2;
    const int pq   = tid & 3;
    const uint32_t pst = (uint32_t)prow * 80u + (uint32_t)pq * 16u;
    const __half* pAh = Ah + (size_t)(row0 + prow) * lda + pq * 8;
    const __half* pAl = Al + (size_t)(row0 + prow) * lda + pq * 8;
    const __half* pBh = Bh + (size_t)(col0 + prow) * ldb + pq * 8;

    // prologue: stages 0..2 (nCh >= 4 for every launch in this problem)
#pragma unroll
    for (int s = 0; s < NSTAGE - 1; s++) {
        const int kO = s * KC;
        const uint32_t st = base + (uint32_t)s * STAGE_B;
        CP16(st + pst,               pAh + kO);
        if (useAl) CP16(st + TILE80 + pst, pAl + kO);
        CP16(st + 2u * TILE80 + pst, pBh + kO);
        CP_COMMIT();
    }

    // acc[mt][g] = n-subtile 2g, acc2[mt][g] = n-subtile 2g+1
    float acc [2][2][4];
    float acc2[2][2][4];
#pragma unroll
    for (int mt = 0; mt < 2; mt++)
#pragma unroll
        for (int g = 0; g < 2; g++)
#pragma unroll
            for (int r = 0; r < 4; r++) { acc[mt][g][r] = 0.f; acc2[mt][g][r] = 0.f; }

    const uint32_t aRow  = (uint32_t)(wm * 32 + (lane & 15));
    const uint32_t aSlot = (uint32_t)(lane >> 4);
    const uint32_t bRow  = (uint32_t)(wn * 32 + (lane & 7) + ((lane >> 4) << 3));
    const uint32_t bSlot = (uint32_t)((lane >> 3) & 1);

    for (int i = 0; i < nCh; i++) {
        CP_WAIT2();                 // chunk i landed
        __syncthreads();            // all warps done with the stage being refilled
        if (i + NSTAGE - 1 < nCh) {
            const int kO = (i + NSTAGE - 1) * KC;
            const uint32_t st =
                base + (uint32_t)((i + NSTAGE - 1) & (NSTAGE - 1)) * STAGE_B;
            CP16(st + pst,               pAh + kO);
            if (useAl) CP16(st + TILE80 + pst, pAl + kO);
            CP16(st + 2u * TILE80 + pst, pBh + kO);
        }
        CP_COMMIT();

        const uint32_t buf = base + (uint32_t)(i & (NSTAGE - 1)) * STAGE_B;
#pragma unroll
        for (int s = 0; s < 2; s++) {
            uint32_t a[2][4];       // Ah, later overwritten by Al
            uint32_t b2[2][4];      // Bh (two subtiles per group)
            // phase 1: Ah x Bh
#pragma unroll
            for (int mt = 0; mt < 2; mt++)
                ldm4(a[mt], buf + (aRow + (uint32_t)(mt * 16)) * 80u
                                + (2u * s + aSlot) * 16u);
#pragma unroll
            for (int g = 0; g < 2; g++)
                ldm4(b2[g], buf + 2u * TILE80
                                + (bRow + (uint32_t)(g * 16)) * 80u
                                + (2u * s + bSlot) * 16u);
#pragma unroll
            for (int mt = 0; mt < 2; mt++)
#pragma unroll
                for (int g = 0; g < 2; g++) {
                    mma16816(acc [mt][g], a[mt], b2[g]);
                    mma16816(acc2[mt][g], a[mt], b2[g] + 2);
                }
            // phase 2: Al x Bh (only when this tile carries the lo term)
            if (useAl) {
#pragma unroll
                for (int mt = 0; mt < 2; mt++)
                    ldm4(a[mt], buf + TILE80
                                    + (aRow + (uint32_t)(mt * 16)) * 80u
                                    + (2u * s + aSlot) * 16u);
#pragma unroll
                for (int mt = 0; mt < 2; mt++)
#pragma unroll
                    for (int g = 0; g < 2; g++) {
                        mma16816(acc [mt][g], a[mt], b2[g]);
                        mma16816(acc2[mt][g], a[mt], b2[g] + 2);
                    }
            }
        }
    }

    // epilogue: group g covers n-subtiles {2g (acc), 2g+1 (acc2)}
#pragma unroll
    for (int mt = 0; mt < 2; mt++) {
        const int rbase = row0 + wm * 32 + mt * 16 + (lane >> 2);
#pragma unroll
        for (int g = 0; g < 2; g++) {
#pragma unroll
            for (int half = 0; half < 2; half++) {
                const float* a4 = half ? acc2[mt][g] : acc[mt][g];
                const int nt = 2 * g + half;
                const int cbase = col0 + wn * 32 + nt * 8 + (lane & 3) * 2;
                float v00 = alpha * a4[0];
                float v01 = alpha * a4[1];
                float v10 = alpha * a4[2];
                float v11 = alpha * a4[3];
                if (flags & 4) {
                    uint32_t h0 = pk2h(v00, v01);
                    uint32_t h1 = pk2h(v10, v11);
                    *(uint32_t*)(Ch + zc + (size_t)rbase * ldc + cbase)       = h0;
                    *(uint32_t*)(Ch + zc + (size_t)(rbase + 8) * ldc + cbase) = h1;
                    if (!(flags & 8)) {
                        uint32_t l0 = pk2h(v00 - h2f_lo(h0), v01 - h2f_hi(h0));
                        uint32_t l1 = pk2h(v10 - h2f_lo(h1), v11 - h2f_hi(h1));
                        *(uint32_t*)(Cl + zc + (size_t)rbase * ldc + cbase)       = l0;
                        *(uint32_t*)(Cl + zc + (size_t)(rbase + 8) * ldc + cbase) = l1;
                    }
                } else {
                    float2 v0; v0.x = v00; v0.y = v01;
                    float2 v1; v1.x = v10; v1.y = v11;
                    *(float2*)(Cf + zc + (size_t)rbase * ldc + cbase)       = v0;
                    *(float2*)(Cf + zc + (size_t)(rbase + 8) * ldc + cbase) = v1;
                }
            }
        }
    }
}

// ---------------------------------------------------------------------------
// Causal softmax in place. Loads only the ceil((r+1)/256) populated column
// blocks; stores full width (zeros beyond nv). Emits f16 P (hi) c < blockend.
// ---------------------------------------------------------------------------
__global__ __launch_bounds__(256) void softmax_causal(
    float* __restrict__ attn, __half* __restrict__ Ph)
{
    const int r = blockIdx.x;
    const int h = blockIdx.y;
    const size_t ro = ((size_t)h * S_LEN + r) * S_LEN;
    float* row = attn + ro;
    const int nv  = r + 1;
    const int nIter = (nv + 255) >> 8;          // populated 256-col blocks
    const int blockend = ((r >> 7) + 1) << 7;   // end of diagonal 128-block
    const int tid = threadIdx.x;

    float v[8];
    float mx = -1e30f;
#pragma unroll
    for (int i = 0; i < 8; i++) {
        v[i] = 0.f;
        if (i < nIter) {
            int c = tid + i * 256;
            float x = (c < nv) ? row[c] : -1e30f;
            v[i] = x;
            mx = fmaxf(mx, x);
        }
    }

    __shared__ float red[256];
    red[tid] = mx;
    __syncthreads();
#pragma unroll
    for (int s2 = 128; s2 > 0; s2 >>= 1) {
        if (tid < s2) red[tid] = fmaxf(red[tid], red[tid + s2]);
        __syncthreads();
    }
    mx = red[0];
    __syncthreads();

    float sum = 0.f;
#pragma unroll
    for (int i = 0; i < 8; i++) {
        if (i < nIter) {
            int c = tid + i * 256;
            v[i] = (c < nv) ? expf(v[i] - mx) : 0.f;
            sum += v[i];
        }
    }
    red[tid] = sum;
    __syncthreads();
#pragma unroll
    for (int s2 = 128; s2 > 0; s2 >>= 1) {
        if (tid < s2) red[tid] += red[tid + s2];
        __syncthreads();
    }
    const float inv = 1.f / red[0];

#pragma unroll
    for (int i = 0; i < 8; i++) {
        int c = tid + i * 256;
        float val = v[i] * inv;     // exact 0 beyond loaded region
        row[c] = val;
        if (c < blockend) Ph[ro + c] = __float2half_rn(val);
    }
}

// ---------------------------------------------------------------------------
// Launch
// Inputs: hidden_states, cos, sin, attention_mask, w_qkv, w_o
// Output: [out (1,2048,3072)] ++ [attn_weights (1,24,2048,2048)]
// ---------------------------------------------------------------------------
extern "C" void kernel_launch(void* const* d_in, const int* in_sizes, int n_in,
                              void* d_out, int out_size)
{
    const float* hidden = (const float*)d_in[0];
    const float* cosb   = (const float*)d_in[1];
    const float* sinb   = (const float*)d_in[2];
    const float* wqkv   = (const float*)d_in[4];
    const float* wo     = (const float*)d_in[5];

    float* out  = (float*)d_out;
    float* attn = out + (size_t)S_LEN * HID;

    float* qkv;
    __half *hidh, *wqkvh, *woh;
    __half *qkh, *qkl, *vTh, *Ph, *aoh;
    cudaGetSymbolAddress((void**)&qkv,   g_qkv);
    cudaGetSymbolAddress((void**)&hidh,  g_hidh);
    cudaGetSymbolAddress((void**)&wqkvh, g_wqkvh);
    cudaGetSymbolAddress((void**)&woh,   g_woh);
    cudaGetSymbolAddress((void**)&qkh,   g_qkh);
    cudaGetSymbolAddress((void**)&qkl,   g_qkl);
    cudaGetSymbolAddress((void**)&vTh,   g_vTh);
    cudaGetSymbolAddress((void**)&Ph,    g_Ph);
    cudaGetSymbolAddress((void**)&aoh,   g_aoh);

    cudaFuncSetAttribute(gemm_f16, cudaFuncAttributeMaxDynamicSharedMemorySize,
                         GEMM_SMEM);

    // one-time side stream + events for overlapping the w_o split
    static cudaStream_t s2 = nullptr;
    static cudaEvent_t evF = nullptr, evJ = nullptr;
    if (!s2) {
        cudaStreamCreateWithFlags(&s2, cudaStreamNonBlocking);
        cudaEventCreateWithFlags(&evF, cudaEventDisableTiming);
        cudaEventCreateWithFlags(&evJ, cudaEventDisableTiming);
    }

    // fork: w_o split runs on s2, overlapped with main-stream work
    cudaEventRecord(evF, 0);
    cudaStreamWaitEvent(s2, evF, 0);
    conv_split_h<<<(HID * HID / 4 + 255) / 256, 256, 0, s2>>>(
        wo, woh, HID * HID / 4);
    cudaEventRecord(evJ, s2);

    // 0. operand splits needed before QKV (main stream, both hi-only now)
    conv_split_h<<<(S_LEN * HID / 4 + 255) / 256, 256>>>(hidden, hidh,
                                                         S_LEN * HID / 4);
    conv_split_h<<<(OPSZ * HID / 4 + 255) / 256, 256>>>(wqkv, wqkvh,
                                                        OPSZ * HID / 4);

    // 1. qkv = hidden @ w_qkv^T   (2048 x 5120, K=3072), fp32 out, 1-term
    gemm_f16<<<dim3(OPSZ / 128, S_LEN / 128, 1), 512, GEMM_SMEM>>>(
        hidh, hidh, HID, 0, wqkvh, HID, 0, 1,
        qkv, nullptr, nullptr, OPSZ, 0, HID, 1.0f, 0, 0);

    // 2. RoPE + split Q(hi/lo)/K(hi);  3. transpose + split V (hi)
    rope_split<<<S_LEN * 1024 / 256, 256>>>(qkv, cosb, sinb, qkh, qkl);
    vsplit_T<<<dim3((NKV * HD) / 32, S_LEN / 32), dim3(32, 8)>>>(qkv, vTh);

    // 4. scores = Q K^T * scale (causal tiles only) -> attn fp32 (2-term A)
    gemm_f16<<<dim3(S_LEN / 128, S_LEN / 128, NH), 512, GEMM_SMEM>>>(
        qkh, qkl, QK_COLS, HD,
        qkh + HID, QK_COLS, HD, 3,
        attn, nullptr, nullptr, S_LEN, (long long)S_LEN * S_LEN,
        HD, SCALING, 1, 1 << 30);

    // 5. softmax in place (trimmed loads, full-width stores) + P hi emit
    softmax_causal<<<dim3(S_LEN, NH), 256>>>(attn, Ph);

    // 6. ao(hi) = P @ V (K limited to row0+128; 1-term)
    gemm_f16<<<dim3(HD / 128, S_LEN / 128, NH), 512, GEMM_SMEM>>>(
        Ph, Ph, S_LEN, (long long)S_LEN * S_LEN,
        vTh, S_LEN, (long long)HD * S_LEN, 3,
        nullptr, aoh, nullptr, HID, HD,
        S_LEN, 1.0f, 2 | 4 | 8, 0);

    // join: w_o split must be done before the out-proj GEMM
    cudaStreamWaitEvent(0, evJ, 0);

    // 7. out = ao @ w_o^T (1-term)
    gemm_f16<<<dim3(HID / 128, S_LEN / 128, 1), 512, GEMM_SMEM>>>(
        aoh, aoh, HID, 0, woh, HID, 0, 1,
        out, nullptr, nullptr, HID, 0, HID, 1.0f, 0, 0);
}

// round 17
// speedup vs baseline: 1.1421x; 1.0826x over previous
#include <cuda_runtime.h>
#include <cuda_fp16.h>
#include <cstdint>

#define S_LEN 2048
#define HID 3072
#define NH 24
#define NKV 8
#define HD 128
#define OPSZ 5120
#define QK_COLS 4096
#define SCALING 0.08838834764831845f

// ---------------------------------------------------------------------------
// Scratch (__device__ globals; runtime allocation forbidden)
// ---------------------------------------------------------------------------
__device__ float  g_qkv[(size_t)S_LEN * OPSZ];                                 // 42 MB
__device__ __half g_hidh [(size_t)S_LEN * HID];                                // hi only
__device__ __half g_wqkvh[(size_t)OPSZ * HID];                                 // B: hi only
__device__ __half g_woh  [(size_t)HID * HID];                                  // B: hi only
__device__ __half g_qkh  [(size_t)S_LEN * QK_COLS], g_qkl[(size_t)S_LEN * QK_COLS];
__device__ __half g_vTh  [(size_t)NKV * HD * S_LEN];                           // B: hi only
__device__ __half g_Ph   [(size_t)NH * S_LEN * S_LEN];                         // 201 MB (hi only)
__device__ __half g_aoh  [(size_t)S_LEN * HID];                                // hi only

// ---------------------------------------------------------------------------
// helpers
// ---------------------------------------------------------------------------
__device__ __forceinline__ uint32_t smem_u32(const void* p) {
    uint32_t a;
    asm("{ .reg .u64 t; cvta.to.shared.u64 t, %1; cvt.u32.u64 %0, t; }"
        : "=r"(a) : "l"(p));
    return a;
}
__device__ __forceinline__ void ldm4(uint32_t* r, uint32_t addr) {
    asm volatile("ldmatrix.sync.aligned.m8n8.x4.shared.b16 {%0,%1,%2,%3}, [%4];"
        : "=r"(r[0]), "=r"(r[1]), "=r"(r[2]), "=r"(r[3]) : "r"(addr));
}
__device__ __forceinline__ void mma16816(float* c, const uint32_t* a,
                                         const uint32_t* b) {
    asm volatile(
        "mma.sync.aligned.m16n8k16.row.col.f32.f16.f16.f32 "
        "{%0,%1,%2,%3}, {%4,%5,%6,%7}, {%8,%9}, {%0,%1,%2,%3};"
        : "+f"(c[0]), "+f"(c[1]), "+f"(c[2]), "+f"(c[3])
        : "r"(a[0]), "r"(a[1]), "r"(a[2]), "r"(a[3]), "r"(b[0]), "r"(b[1]));
}
// pack two fp32 -> f16x2 (lo half = a, hi half = b), round-to-nearest
__device__ __forceinline__ uint32_t pk2h(float a, float b) {
    uint32_t r;
    asm("cvt.rn.f16x2.f32 %0, %1, %2;" : "=r"(r) : "f"(b), "f"(a));
    return r;
}
__device__ __forceinline__ float h2f_lo(uint32_t p) {
    return __half2float(__ushort_as_half((unsigned short)(p & 0xffffu)));
}
__device__ __forceinline__ float h2f_hi(uint32_t p) {
    return __half2float(__ushort_as_half((unsigned short)(p >> 16)));
}
#define CP16(dst, src) \
    asm volatile("cp.async.cg.shared.global [%0], [%1], 16;" \
                 :: "r"(dst), "l"(src) : "memory")
#define CP_COMMIT() asm volatile("cp.async.commit_group;" ::: "memory")
#define CP_WAIT2()  asm volatile("cp.async.wait_group 2;" ::: "memory")

// fp32 -> f16 hi only, 4 elems/thread
__global__ __launch_bounds__(256) void conv_split_h(
    const float* __restrict__ src, __half* __restrict__ h, int n4)
{
    int i = blockIdx.x * 256 + threadIdx.x;
    if (i >= n4) return;
    float4 x = ((const float4*)src)[i];
    uint2 hh; hh.x = pk2h(x.x, x.y); hh.y = pk2h(x.z, x.w);
    ((uint2*)h)[i] = hh;
}

// ---------------------------------------------------------------------------
// Fused RoPE + split on Q/K columns (0..4095). Q cols get hi+lo, K hi only.
// ---------------------------------------------------------------------------
__global__ __launch_bounds__(256) void rope_split(
    const float* __restrict__ qkv, const float* __restrict__ cosb,
    const float* __restrict__ sinb,
    __half* __restrict__ qh, __half* __restrict__ ql)
{
    int idx = blockIdx.x * 256 + threadIdx.x;   // S_LEN * 1024
    int s = idx >> 10;
    int c = (idx & 1023) * 4;
    int d = c & 127;
    const float* row = qkv + (size_t)s * OPSZ;
    float4 x = *(const float4*)(row + c);
    if (d < 96) {
        float4 cc = *(const float4*)(cosb + s * 96 + d);
        float4 ss = *(const float4*)(sinb + s * 96 + d);
        if (d < 48) {
            float4 p = *(const float4*)(row + c + 48);
            x.x = x.x * cc.x - p.x * ss.x;
            x.y = x.y * cc.y - p.y * ss.y;
            x.z = x.z * cc.z - p.z * ss.z;
            x.w = x.w * cc.w - p.w * ss.w;
        } else {
            float4 p = *(const float4*)(row + c - 48);
            x.x = x.x * cc.x + p.x * ss.x;
            x.y = x.y * cc.y + p.y * ss.y;
            x.z = x.z * cc.z + p.z * ss.z;
            x.w = x.w * cc.w + p.w * ss.w;
        }
    }
    uint32_t p0 = pk2h(x.x, x.y), p1 = pk2h(x.z, x.w);
    size_t o = ((size_t)s * QK_COLS + c) >> 2;
    uint2 hh; hh.x = p0; hh.y = p1;
    ((uint2*)qh)[o] = hh;
    if (c < HID) {                      // lo needed only for Q (A-side)
        float l0 = x.x - h2f_lo(p0);
        float l1 = x.y - h2f_hi(p0);
        float l2 = x.z - h2f_lo(p1);
        float l3 = x.w - h2f_hi(p1);
        uint2 ll; ll.x = pk2h(l0, l1); ll.y = pk2h(l2, l3);
        ((uint2*)ql)[o] = ll;
    }
}

// ---------------------------------------------------------------------------
// V transpose + split (hi only): vT[kv*HD+d][s] = qkv[s][4096+kv*HD+d]
// ---------------------------------------------------------------------------
__global__ __launch_bounds__(256) void vsplit_T(
    const float* __restrict__ qkv, __half* __restrict__ vh)
{
    __shared__ float tile[32][33];
    const int t0 = blockIdx.x * 32;
    const int s0 = blockIdx.y * 32;
    const int tx = threadIdx.x, ty = threadIdx.y;   // (32, 8)
#pragma unroll
    for (int j = 0; j < 4; j++)
        tile[ty + 8 * j][tx] =
            qkv[(size_t)(s0 + ty + 8 * j) * OPSZ + 4096 + t0 + tx];
    __syncthreads();
#pragma unroll
    for (int j = 0; j < 4; j++) {
        float v = tile[tx][ty + 8 * j];
        vh[(size_t)(t0 + ty + 8 * j) * S_LEN + s0 + tx] = __float2half_rn(v);
    }
}

// ---------------------------------------------------------------------------
// Generic NT GEMM, fp16: C = alpha * (Ah [+Al]) [M,K] * Bh[N,K]^T
// Al term applied only for tiles with col0 < nloCols (per-tile term count).
// rowOff/colOff: global offsets for sliced launches (keep causal semantics).
// 128x128 tile, 512 threads (16 warps, warp tile 32x32), KC=32,
// 4-stage cp.async pipeline, 80B SMEM row pitch.
// flags: 1 = causal tile skip, 2 = K limited to row0+128,
//        4 = f16 split output (hi to Ch; lo to Cl only if !(flags&8)).
// ---------------------------------------------------------------------------
#define KC 32
#define TILE80 10240u              // 128 rows * 80 B
#define STAGE_B (3u * TILE80)      // Ah Al Bh = 30720
#define NSTAGE  4
#define GEMM_SMEM (NSTAGE * STAGE_B)   // 122880

__global__ __launch_bounds__(512) void gemm_f16(
    const __half* __restrict__ Ah, const __half* __restrict__ Al,
    int lda, long long sAz,
    const __half* __restrict__ Bh, int ldb, long long sBz, int kvdiv,
    float* __restrict__ Cf, __half* __restrict__ Ch,
    __half* __restrict__ Cl, int ldc, long long sCz,
    int K, float alpha, int flags, int nloCols, int rowOff, int colOff)
{
    const int row0 = (blockIdx.y << 7) + rowOff;
    const int col0 = (blockIdx.x << 7) + colOff;
    if ((flags & 1) && col0 > row0) return;
    const bool useAl = (col0 < nloCols);
    const int z = blockIdx.z;
    const size_t za = (size_t)z * sAz;
    const size_t zb = (size_t)(z / kvdiv) * sBz;
    const size_t zc = (size_t)z * sCz;
    Ah += za; Al += za; Bh += zb;
    const int Keff = (flags & 2) ? ((K < row0 + 128) ? K : row0 + 128) : K;
    const int nCh  = Keff >> 5;

    extern __shared__ char smem[];
    const uint32_t base = smem_u32(smem);

    const int tid  = threadIdx.x;
    const int warp = tid >> 5;
    const int lane = tid & 31;
    const int wm   = warp >> 2;      // 0..3
    const int wn   = warp & 3;       // 0..3

    // producer mapping: row = tid>>2 (0..127), 16B chunk = tid&3
    const int prow = tid >> 2;
    const int pq   = tid & 3;
    const uint32_t pst = (uint32_t)prow * 80u + (uint32_t)pq * 16u;
    const __half* pAh = Ah + (size_t)(row0 + prow) * lda + pq * 8;
    const __half* pAl = Al + (size_t)(row0 + prow) * lda + pq * 8;
    const __half* pBh = Bh + (size_t)(col0 + prow) * ldb + pq * 8;

    // prologue: stages 0..2 (nCh >= 4 for every launch in this problem)
#pragma unroll
    for (int s = 0; s < NSTAGE - 1; s++) {
        const int kO = s * KC;
        const uint32_t st = base + (uint32_t)s * STAGE_B;
        CP16(st + pst,               pAh + kO);
        if (useAl) CP16(st + TILE80 + pst, pAl + kO);
        CP16(st + 2u * TILE80 + pst, pBh + kO);
        CP_COMMIT();
    }

    // acc[mt][g] = n-subtile 2g, acc2[mt][g] = n-subtile 2g+1
    float acc [2][2][4];
    float acc2[2][2][4];
#pragma unroll
    for (int mt = 0; mt < 2; mt++)
#pragma unroll
        for (int g = 0; g < 2; g++)
#pragma unroll
            for (int r = 0; r < 4; r++) { acc[mt][g][r] = 0.f; acc2[mt][g][r] = 0.f; }

    const uint32_t aRow  = (uint32_t)(wm * 32 + (lane & 15));
    const uint32_t aSlot = (uint32_t)(lane >> 4);
    const uint32_t bRow  = (uint32_t)(wn * 32 + (lane & 7) + ((lane >> 4) << 3));
    const uint32_t bSlot = (uint32_t)((lane >> 3) & 1);

    for (int i = 0; i < nCh; i++) {
        CP_WAIT2();                 // chunk i landed
        __syncthreads();            // all warps done with the stage being refilled
        if (i + NSTAGE - 1 < nCh) {
            const int kO = (i + NSTAGE - 1) * KC;
            const uint32_t st =
                base + (uint32_t)((i + NSTAGE - 1) & (NSTAGE - 1)) * STAGE_B;
            CP16(st + pst,               pAh + kO);
            if (useAl) CP16(st + TILE80 + pst, pAl + kO);
            CP16(st + 2u * TILE80 + pst, pBh + kO);
        }
        CP_COMMIT();

        const uint32_t buf = base + (uint32_t)(i & (NSTAGE - 1)) * STAGE_B;
#pragma unroll
        for (int s = 0; s < 2; s++) {
            uint32_t a[2][4];       // Ah, later overwritten by Al
            uint32_t b2[2][4];      // Bh (two subtiles per group)
            // phase 1: Ah x Bh
#pragma unroll
            for (int mt = 0; mt < 2; mt++)
                ldm4(a[mt], buf + (aRow + (uint32_t)(mt * 16)) * 80u
                                + (2u * s + aSlot) * 16u);
#pragma unroll
            for (int g = 0; g < 2; g++)
                ldm4(b2[g], buf + 2u * TILE80
                                + (bRow + (uint32_t)(g * 16)) * 80u
                                + (2u * s + bSlot) * 16u);
#pragma unroll
            for (int mt = 0; mt < 2; mt++)
#pragma unroll
                for (int g = 0; g < 2; g++) {
                    mma16816(acc [mt][g], a[mt], b2[g]);
                    mma16816(acc2[mt][g], a[mt], b2[g] + 2);
                }
            // phase 2: Al x Bh (only when this tile carries the lo term)
            if (useAl) {
#pragma unroll
                for (int mt = 0; mt < 2; mt++)
                    ldm4(a[mt], buf + TILE80
                                    + (aRow + (uint32_t)(mt * 16)) * 80u
                                    + (2u * s + aSlot) * 16u);
#pragma unroll
                for (int mt = 0; mt < 2; mt++)
#pragma unroll
                    for (int g = 0; g < 2; g++) {
                        mma16816(acc [mt][g], a[mt], b2[g]);
                        mma16816(acc2[mt][g], a[mt], b2[g] + 2);
                    }
            }
        }
    }

    // epilogue: group g covers n-subtiles {2g (acc), 2g+1 (acc2)}
#pragma unroll
    for (int mt = 0; mt < 2; mt++) {
        const int rbase = row0 + wm * 32 + mt * 16 + (lane >> 2);
#pragma unroll
        for (int g = 0; g < 2; g++) {
#pragma unroll
            for (int half = 0; half < 2; half++) {
                const float* a4 = half ? acc2[mt][g] : acc[mt][g];
                const int nt = 2 * g + half;
                const int cbase = col0 + wn * 32 + nt * 8 + (lane & 3) * 2;
                float v00 = alpha * a4[0];
                float v01 = alpha * a4[1];
                float v10 = alpha * a4[2];
                float v11 = alpha * a4[3];
                if (flags & 4) {
                    uint32_t h0 = pk2h(v00, v01);
                    uint32_t h1 = pk2h(v10, v11);
                    *(uint32_t*)(Ch + zc + (size_t)rbase * ldc + cbase)       = h0;
                    *(uint32_t*)(Ch + zc + (size_t)(rbase + 8) * ldc + cbase) = h1;
                    if (!(flags & 8)) {
                        uint32_t l0 = pk2h(v00 - h2f_lo(h0), v01 - h2f_hi(h0));
                        uint32_t l1 = pk2h(v10 - h2f_lo(h1), v11 - h2f_hi(h1));
                        *(uint32_t*)(Cl + zc + (size_t)rbase * ldc + cbase)       = l0;
                        *(uint32_t*)(Cl + zc + (size_t)(rbase + 8) * ldc + cbase) = l1;
                    }
                } else {
                    float2 v0; v0.x = v00; v0.y = v01;
                    float2 v1; v1.x = v10; v1.y = v11;
                    *(float2*)(Cf + zc + (size_t)rbase * ldc + cbase)       = v0;
                    *(float2*)(Cf + zc + (size_t)(rbase + 8) * ldc + cbase) = v1;
                }
            }
        }
    }
}

// ---------------------------------------------------------------------------
// Causal softmax in place. Loads only the ceil((r+1)/256) populated column
// blocks; stores full width (zeros beyond nv). Emits f16 P (hi) c < blockend.
// ---------------------------------------------------------------------------
__global__ __launch_bounds__(256) void softmax_causal(
    float* __restrict__ attn, __half* __restrict__ Ph)
{
    const int r = blockIdx.x;
    const int h = blockIdx.y;
    const size_t ro = ((size_t)h * S_LEN + r) * S_LEN;
    float* row = attn + ro;
    const int nv  = r + 1;
    const int nIter = (nv + 255) >> 8;          // populated 256-col blocks
    const int blockend = ((r >> 7) + 1) << 7;   // end of diagonal 128-block
    const int tid = threadIdx.x;

    float v[8];
    float mx = -1e30f;
#pragma unroll
    for (int i = 0; i < 8; i++) {
        v[i] = 0.f;
        if (i < nIter) {
            int c = tid + i * 256;
            float x = (c < nv) ? row[c] : -1e30f;
            v[i] = x;
            mx = fmaxf(mx, x);
        }
    }

    __shared__ float red[256];
    red[tid] = mx;
    __syncthreads();
#pragma unroll
    for (int s2 = 128; s2 > 0; s2 >>= 1) {
        if (tid < s2) red[tid] = fmaxf(red[tid], red[tid + s2]);
        __syncthreads();
    }
    mx = red[0];
    __syncthreads();

    float sum = 0.f;
#pragma unroll
    for (int i = 0; i < 8; i++) {
        if (i < nIter) {
            int c = tid + i * 256;
            v[i] = (c < nv) ? expf(v[i] - mx) : 0.f;
            sum += v[i];
        }
    }
    red[tid] = sum;
    __syncthreads();
#pragma unroll
    for (int s2 = 128; s2 > 0; s2 >>= 1) {
        if (tid < s2) red[tid] += red[tid + s2];
        __syncthreads();
    }
    const float inv = 1.f / red[0];

#pragma unroll
    for (int i = 0; i < 8; i++) {
        int c = tid + i * 256;
        float val = v[i] * inv;     // exact 0 beyond loaded region
        row[c] = val;
        if (c < blockend) Ph[ro + c] = __float2half_rn(val);
    }
}

// ---------------------------------------------------------------------------
// Launch
// Inputs: hidden_states, cos, sin, attention_mask, w_qkv, w_o
// Output: [out (1,2048,3072)] ++ [attn_weights (1,24,2048,2048)]
// ---------------------------------------------------------------------------
extern "C" void kernel_launch(void* const* d_in, const int* in_sizes, int n_in,
                              void* d_out, int out_size)
{
    const float* hidden = (const float*)d_in[0];
    const float* cosb   = (const float*)d_in[1];
    const float* sinb   = (const float*)d_in[2];
    const float* wqkv   = (const float*)d_in[4];
    const float* wo     = (const float*)d_in[5];

    float* out  = (float*)d_out;
    float* attn = out + (size_t)S_LEN * HID;

    float* qkv;
    __half *hidh, *wqkvh, *woh;
    __half *qkh, *qkl, *vTh, *Ph, *aoh;
    cudaGetSymbolAddress((void**)&qkv,   g_qkv);
    cudaGetSymbolAddress((void**)&hidh,  g_hidh);
    cudaGetSymbolAddress((void**)&wqkvh, g_wqkvh);
    cudaGetSymbolAddress((void**)&woh,   g_woh);
    cudaGetSymbolAddress((void**)&qkh,   g_qkh);
    cudaGetSymbolAddress((void**)&qkl,   g_qkl);
    cudaGetSymbolAddress((void**)&vTh,   g_vTh);
    cudaGetSymbolAddress((void**)&Ph,    g_Ph);
    cudaGetSymbolAddress((void**)&aoh,   g_aoh);

    cudaFuncSetAttribute(gemm_f16, cudaFuncAttributeMaxDynamicSharedMemorySize,
                         GEMM_SMEM);

    // one-time streams + events
    static cudaStream_t s2 = nullptr;
    static cudaEvent_t evF = nullptr, evJ = nullptr, evS = nullptr,
                       evSM = nullptr, evVT = nullptr, evB = nullptr;
    if (!s2) {
        cudaStreamCreateWithFlags(&s2, cudaStreamNonBlocking);
        cudaEventCreateWithFlags(&evF,  cudaEventDisableTiming);
        cudaEventCreateWithFlags(&evJ,  cudaEventDisableTiming);
        cudaEventCreateWithFlags(&evS,  cudaEventDisableTiming);
        cudaEventCreateWithFlags(&evSM, cudaEventDisableTiming);
        cudaEventCreateWithFlags(&evVT, cudaEventDisableTiming);
        cudaEventCreateWithFlags(&evB,  cudaEventDisableTiming);
    }

    const long long SS = (long long)S_LEN * S_LEN;

    // fork s2: w_o split (overlaps the main-stream splits)
    cudaEventRecord(evF, 0);
    cudaStreamWaitEvent(s2, evF, 0);
    conv_split_h<<<(HID * HID / 4 + 255) / 256, 256, 0, s2>>>(
        wo, woh, HID * HID / 4);
    cudaEventRecord(evJ, s2);

    // main: splits needed before QKV
    conv_split_h<<<(S_LEN * HID / 4 + 255) / 256, 256>>>(hidden, hidh,
                                                         S_LEN * HID / 4);
    conv_split_h<<<(OPSZ * HID / 4 + 255) / 256, 256>>>(wqkv, wqkvh,
                                                        OPSZ * HID / 4);
    cudaEventRecord(evS, 0);

    // s2: QKV V-cols part (cols 4096..5119, 128 CTAs) -> vsplit_T
    //     (backfills the QK-part tail and runs under rope/QK)
    cudaStreamWaitEvent(s2, evS, 0);
    gemm_f16<<<dim3(8, S_LEN / 128, 1), 512, GEMM_SMEM, s2>>>(
        hidh, hidh, HID, 0, wqkvh, HID, 0, 1,
        qkv, nullptr, nullptr, OPSZ, 0, HID, 1.0f, 0, 0, 0, 4096);
    vsplit_T<<<dim3((NKV * HD) / 32, S_LEN / 32), dim3(32, 8), 0, s2>>>(qkv, vTh);
    cudaEventRecord(evVT, s2);

    // main: QKV QK-cols part (cols 0..4095, 512 CTAs)
    gemm_f16<<<dim3(32, S_LEN / 128, 1), 512, GEMM_SMEM>>>(
        hidh, hidh, HID, 0, wqkvh, HID, 0, 1,
        qkv, nullptr, nullptr, OPSZ, 0, HID, 1.0f, 0, 0, 0, 0);

    // main: RoPE + split Q(hi/lo)/K(hi) — needs only QK cols
    rope_split<<<S_LEN * 1024 / 256, 256>>>(qkv, cosb, sinb, qkh, qkl);

    // main: scores = Q K^T * scale (causal tiles only), 2-term A
    gemm_f16<<<dim3(S_LEN / 128, S_LEN / 128, NH), 512, GEMM_SMEM>>>(
        qkh, qkl, QK_COLS, HD,
        qkh + HID, QK_COLS, HD, 3,
        attn, nullptr, nullptr, S_LEN, SS,
        HD, SCALING, 1, 1 << 30, 0, 0);

    // main: softmax (trimmed loads) + P hi emit
    softmax_causal<<<dim3(S_LEN, NH), 256>>>(attn, Ph);
    cudaEventRecord(evSM, 0);

    // s2: PV_b (rows 1024..2047) -> outproj_b (rows 1024..2047)
    cudaStreamWaitEvent(s2, evSM, 0);
    gemm_f16<<<dim3(HD / 128, 8, NH), 512, GEMM_SMEM, s2>>>(
        Ph, Ph, S_LEN, SS,
        vTh, S_LEN, (long long)HD * S_LEN, 3,
        nullptr, aoh, nullptr, HID, HD,
        S_LEN, 1.0f, 2 | 4 | 8, 0, 1024, 0);
    gemm_f16<<<dim3(HID / 128, 8, 1), 512, GEMM_SMEM, s2>>>(
        aoh, aoh, HID, 0, woh, HID, 0, 1,
        out, nullptr, nullptr, HID, 0, HID, 1.0f, 0, 0, 1024, 0);
    cudaEventRecord(evB, s2);

    // main: PV_a (rows 0..1023) -> outproj_a (rows 0..1023)
    cudaStreamWaitEvent(0, evVT, 0);
    gemm_f16<<<dim3(HD / 128, 8, NH), 512, GEMM_SMEM>>>(
        Ph, Ph, S_LEN, SS,
        vTh, S_LEN, (long long)HD * S_LEN, 3,
        nullptr, aoh, nullptr, HID, HD,
        S_LEN, 1.0f, 2 | 4 | 8, 0, 0, 0);
    cudaStreamWaitEvent(0, evJ, 0);
    gemm_f16<<<dim3(HID / 128, 8, 1), 512, GEMM_SMEM>>>(
        aoh, aoh, HID, 0, woh, HID, 0, 1,
        out, nullptr, nullptr, HID, 0, HID, 1.0f, 0, 0, 0, 0);

    // join s2 (outproj_b) into the graph's terminal stream
    cudaStreamWaitEvent(0, evB, 0);
}